// round 8
// baseline (speedup 1.0000x reference)
#include <cuda_runtime.h>

#define N_SEG   65536
#define TOTAL   2097152
#define D       128
#define THREADS 64
#define CTAS_PER_SM 23
#define NSM     152
#define GRID    (NSM * CTAS_PER_SM)            /* 3496 CTAs, fully resident */
#define NWARPS  (GRID * (THREADS / 32))        /* 6992 persistent warps */

// 1 -> indptr is int32, 0 -> indptr is int64
__device__ int g_indptr_is32;

__global__ void detect_dtype_kernel(const int* __restrict__ indptr32) {
    // Safe probe: word 65536 exists in both layouts.
    // int32 layout: indptr32[65536] == TOTAL (last element).
    // int64 layout: indptr32[65536] == high word of indptr[32768] == 0.
    g_indptr_is32 = (indptr32[N_SEG] == TOTAL) ? 1 : 0;
}

__device__ __forceinline__ void acc4(float4& a, const float4 v) {
    a.x += v.x; a.y += v.y; a.z += v.z; a.w += v.w;
}

__global__ __launch_bounds__(THREADS, CTAS_PER_SM)
void segment_csr_kernel(const float* __restrict__ x,
                        const void* __restrict__ indptr_raw,
                        float* __restrict__ out) {
    const int warp = blockIdx.x * (THREADS / 32) + (threadIdx.x >> 5);
    const int lane = threadIdx.x & 31;
    const bool is32 = (g_indptr_is32 != 0);

    // lane l owns columns [4l,4l+4): each row is one fully-coalesced 512B
    // warp transaction.
    const float4* xr = reinterpret_cast<const float4*>(x) + lane;
    float4* outr = reinterpret_cast<float4*>(out) + lane;

    // Persistent warp: static stride over segments. ~9.4 segments/warp
    // aggregates the exponential length distribution (sigma 100% -> 33%),
    // shrinking the retirement/drain tail. No atomics, no extra waves.
    for (int seg = warp; seg < N_SEG; seg += NWARPS) {
        int s, e;
        if (is32) {
            const int* p = (const int*)indptr_raw;
            s = p[seg]; e = p[seg + 1];
        } else {
            const long long* p = (const long long*)indptr_raw;
            s = (int)p[seg]; e = (int)p[seg + 1];
        }

        float4 a0 = make_float4(0.f, 0.f, 0.f, 0.f);
        float4 a1 = make_float4(0.f, 0.f, 0.f, 0.f);
        float4 a2 = make_float4(0.f, 0.f, 0.f, 0.f);
        float4 a3 = make_float4(0.f, 0.f, 0.f, 0.f);

        int r = s;
        // 4 independent LDG.128 in flight per iteration.
        for (; r + 4 <= e; r += 4) {
            const float4 v0 = __ldcs(xr + (size_t)(r    ) * 32);
            const float4 v1 = __ldcs(xr + (size_t)(r + 1) * 32);
            const float4 v2 = __ldcs(xr + (size_t)(r + 2) * 32);
            const float4 v3 = __ldcs(xr + (size_t)(r + 3) * 32);
            acc4(a0, v0); acc4(a1, v1); acc4(a2, v2); acc4(a3, v3);
        }
        for (; r < e; ++r) {
            acc4(a0, __ldcs(xr + (size_t)r * 32));
        }
        acc4(a0, a1); acc4(a2, a3); acc4(a0, a2);

        __stcs(outr + (size_t)seg * 32, a0);
    }
}

extern "C" void kernel_launch(void* const* d_in, const int* in_sizes, int n_in,
                              void* d_out, int out_size) {
    const float* x     = (const float*)d_in[0];
    const void* indptr = d_in[1];
    float* out         = (float*)d_out;

    detect_dtype_kernel<<<1, 1>>>((const int*)indptr);
    segment_csr_kernel<<<GRID, THREADS>>>(x, indptr, out);
}

// round 9
// speedup vs baseline: 1.1552x; 1.1552x over previous
#include <cuda_runtime.h>

#define N_SEG   65536
#define TOTAL   2097152
#define THREADS 64
#define CTAS_PER_SM 20
#define NSM     152
#define GRID    (NSM * CTAS_PER_SM)      /* 3040 CTAs, one resident wave */
#define NWARPS  (GRID * 2)               /* 6080 warps */
#define RPW     345                      /* ceil(TOTAL / NWARPS) rows per warp */

// 1 -> indptr is int32, 0 -> indptr is int64
__device__ int g_indptr_is32;

__global__ void detect_dtype_kernel(const int* __restrict__ indptr32) {
    // int32 layout: word 65536 == TOTAL (last element).
    // int64 layout: word 65536 == high word of indptr[32768] == 0.
    g_indptr_is32 = (indptr32[N_SEG] == TOTAL) ? 1 : 0;
}

__device__ __forceinline__ int ipr(const void* p, bool is32, int i) {
    return is32 ? ((const int*)p)[i] : (int)((const long long*)p)[i];
}

// first i in [0, N_SEG] with indptr[i] >= target
__device__ __forceinline__ int lb(const void* p, bool is32, int target) {
    int lo = 0, hi = N_SEG;
    while (lo < hi) {
        int m = (lo + hi) >> 1;
        if (ipr(p, is32, m) < target) lo = m + 1;
        else hi = m;
    }
    return lo;
}

// Zero only the segments that straddle a warp-range boundary (these receive
// atomicAdd partials from multiple warps). Runs before the main kernel on
// every launch, so graph replays remain correct.
__global__ void zero_straddlers_kernel(const void* __restrict__ indptr_raw,
                                       float4* __restrict__ out4) {
    const int w = blockIdx.x * blockDim.x + threadIdx.x + 1;  // boundary 1..NWARPS-1
    if (w >= NWARPS) return;
    const bool is32 = (g_indptr_is32 != 0);
    const int b = w * RPW;
    if (b >= TOTAL) return;
    const int A = lb(indptr_raw, is32, b);     // first seg with start >= b
    // Segment A-1 straddles b iff its end (= indptr[A]) > b.
    if (A >= 1 && ipr(indptr_raw, is32, A) > b) {
        float4* o = out4 + (size_t)(A - 1) * 32;
        const float4 z = make_float4(0.f, 0.f, 0.f, 0.f);
        #pragma unroll
        for (int k = 0; k < 32; ++k) o[k] = z;
    }
}

__device__ __forceinline__ void acc4(float4& a, const float4 v) {
    a.x += v.x; a.y += v.y; a.z += v.z; a.w += v.w;
}

__global__ __launch_bounds__(THREADS, CTAS_PER_SM)
void segment_csr_kernel(const float* __restrict__ x,
                        const void* __restrict__ indptr_raw,
                        float* __restrict__ out) {
    const int w    = blockIdx.x * 2 + (threadIdx.x >> 5);
    const int lane = threadIdx.x & 31;
    const bool is32 = (g_indptr_is32 != 0);

    const int r0 = w * RPW;
    if (r0 >= TOTAL) return;
    const int r1 = min(r0 + RPW, TOTAL);
    const bool lastw = (r1 == TOTAL);   // also owns trailing empty segments

    // First segment to process: the one containing r0 (straddler) or the
    // first segment starting at/after r0.
    const int A = lb(indptr_raw, is32, r0);
    int i = (A >= 1 && ipr(indptr_raw, is32, A) > r0) ? A - 1 : A;

    // lane l owns columns [4l,4l+4): each row is one fully-coalesced 512B
    // warp transaction.
    const float4* xr = reinterpret_cast<const float4*>(x) + lane;
    float4* outr = reinterpret_cast<float4*>(out) + lane;

    int start = ipr(indptr_raw, is32, i);
    while (lastw ? (i < N_SEG) : (start < r1)) {
        const int end = ipr(indptr_raw, is32, i + 1);
        const int lo = max(start, r0);
        const int hi = min(end, r1);

        float4 a0 = make_float4(0.f, 0.f, 0.f, 0.f);
        float4 a1 = make_float4(0.f, 0.f, 0.f, 0.f);
        float4 a2 = make_float4(0.f, 0.f, 0.f, 0.f);
        float4 a3 = make_float4(0.f, 0.f, 0.f, 0.f);

        int r = lo;
        // 4 independent LDG.128 in flight per iteration.
        for (; r + 4 <= hi; r += 4) {
            const float4 v0 = __ldcs(xr + (size_t)(r    ) * 32);
            const float4 v1 = __ldcs(xr + (size_t)(r + 1) * 32);
            const float4 v2 = __ldcs(xr + (size_t)(r + 2) * 32);
            const float4 v3 = __ldcs(xr + (size_t)(r + 3) * 32);
            acc4(a0, v0); acc4(a1, v1); acc4(a2, v2); acc4(a3, v3);
        }
        for (; r < hi; ++r) {
            acc4(a0, __ldcs(xr + (size_t)r * 32));
        }
        acc4(a0, a1); acc4(a2, a3); acc4(a0, a2);

        const bool inside = (start >= r0) && (end <= r1);
        if (inside) {
            // Unique owner (segment start lies in this warp's range): store.
            __stcs(outr + (size_t)i * 32, a0);
        } else if (hi > lo) {
            // Straddler: accumulate partial onto pre-zeroed output.
            float* o = out + (size_t)i * 128 + lane * 4;
            atomicAdd(o + 0, a0.x);
            atomicAdd(o + 1, a0.y);
            atomicAdd(o + 2, a0.z);
            atomicAdd(o + 3, a0.w);
        }

        ++i;
        start = end;
    }
}

extern "C" void kernel_launch(void* const* d_in, const int* in_sizes, int n_in,
                              void* d_out, int out_size) {
    const float* x     = (const float*)d_in[0];
    const void* indptr = d_in[1];
    float* out         = (float*)d_out;

    detect_dtype_kernel<<<1, 1>>>((const int*)indptr);
    zero_straddlers_kernel<<<(NWARPS + 255) / 256, 256>>>(indptr, (float4*)out);
    segment_csr_kernel<<<GRID, THREADS>>>(x, indptr, out);
}